// round 10
// baseline (speedup 1.0000x reference)
#include <cuda_runtime.h>

#define NUM_GRAPHS 16384
#define EMB_DIM    128

// Scratch: per-graph start offsets (device globals — no allocation allowed).
__device__ int g_starts_atoms[NUM_GRAPHS + 1];
__device__ int g_starts_frags[NUM_GRAPHS + 1];

// ---------------------------------------------------------------------------
// Fused boundary detection with SECTOR SKIPPING. Each thread owns 16
// consecutive elements. Boundaries are sparse (~16k in 3M elements), so
// first compare idx[base+15] with idx[base-1] (one 32B sector each; the
// predecessor sector is the neighbor thread's last sector -> L2 dedup).
// If equal, the sorted chunk is boundary-free: skip the bulk loads.
// Only ~12% of chunks take the full 128B read -> idx DRAM traffic drops
// from 24 MB to ~8 MB.
//
// Dtype probe (int64 vs int32): interpret as int64 and read element n/4.
// For int32 data that word packs two sorted mid-array ids (high half
// nonzero) -> value >= 2^32. True int64 ids are in [0, NUM_GRAPHS).
// ---------------------------------------------------------------------------
__global__ void fill_starts_fused_kernel(const void* idx_a, int n_a,
                                         const void* idx_f, int n_f,
                                         int nblk_a)
{
    bool frag = (int)blockIdx.x >= nblk_a;
    const void* idxp = frag ? idx_f : idx_a;
    int         n    = frag ? n_f   : n_a;
    int*        starts = frag ? g_starts_frags : g_starts_atoms;
    int blk = frag ? (blockIdx.x - nblk_a) : blockIdx.x;

    int base = (blk * blockDim.x + threadIdx.x) * 16;
    if (base >= n) return;
    int cnt = n - base; if (cnt > 16) cnt = 16;

    const long long* p64 = (const long long*)idxp;
    const int*       p32 = (const int*)idxp;
    long long probe = p64[n / 4];
    bool is64 = (probe >= 0 && probe < NUM_GRAPHS);

    // Cheap boundary test: chunk-last vs predecessor (independent loads).
    int last = is64 ? (int)p64[base + cnt - 1] : p32[base + cnt - 1];
    int prev = (base == 0) ? -1 : (is64 ? (int)p64[base - 1] : p32[base - 1]);

    if (prev == last) {
        // Sorted + endpoints equal -> all 16 values equal -> no boundary.
        if (base + cnt == n) {
            for (int g = last + 1; g <= NUM_GRAPHS; ++g) starts[g] = n;
        }
        return;
    }

    // Boundary chunk (~12%): full read + scan.
    int v[16];
    if (is64) {
        if (cnt == 16) {
            #pragma unroll
            for (int q = 0; q < 4; ++q) {
                longlong4 t = ((const longlong4*)(p64 + base))[q];
                v[q*4+0]=(int)t.x; v[q*4+1]=(int)t.y;
                v[q*4+2]=(int)t.z; v[q*4+3]=(int)t.w;
            }
        } else {
            for (int j = 0; j < cnt; ++j) v[j] = (int)p64[base + j];
        }
    } else {
        if (cnt == 16) {
            #pragma unroll
            for (int q = 0; q < 4; ++q) {
                int4 t = ((const int4*)(p32 + base))[q];
                v[q*4+0]=t.x; v[q*4+1]=t.y; v[q*4+2]=t.z; v[q*4+3]=t.w;
            }
        } else {
            for (int j = 0; j < cnt; ++j) v[j] = p32[base + j];
        }
    }

    for (int j = 0; j < cnt; ++j) {
        int b = v[j];
        for (int g = prev + 1; g <= b; ++g) starts[g] = base + j;
        prev = b;
    }
    if (base + cnt == n) {
        for (int g = prev + 1; g <= NUM_GRAPHS; ++g) starts[g] = n;
    }
}

// ---------------------------------------------------------------------------
// Warp-autonomous segment sum (benched best: 221.5 us, DRAM 87.9%):
// one WARP per (graph, half). 32 lanes x float4 cover a full 512B row;
// 4-deep unroll keeps 4 independent LDG.128 in flight per thread. No shared
// memory, no __syncthreads — the accumulating warp stores its own result.
// ---------------------------------------------------------------------------
__device__ __forceinline__ float4 f4add(float4 a, float4 b) {
    a.x += b.x; a.y += b.y; a.z += b.z; a.w += b.w; return a;
}

__global__ __launch_bounds__(128) void segsum_warp_kernel(
    const float4* __restrict__ xa,
    const float4* __restrict__ xf,
    float* __restrict__ out)
{
    int w    = threadIdx.x >> 5;
    int lane = threadIdx.x & 31;

    int item = blockIdx.x * 4 + w;
    if (item >= 2 * NUM_GRAPHS) return;

    bool frag = item >= NUM_GRAPHS;
    int gi    = frag ? item - NUM_GRAPHS : item;

    const int* starts = frag ? g_starts_frags : g_starts_atoms;
    const float4* x   = frag ? xf : xa;

    int s = __ldg(&starts[gi]);
    int e = __ldg(&starts[gi + 1]);

    float4 a0 = make_float4(0.f, 0.f, 0.f, 0.f);
    float4 a1 = a0, a2 = a0, a3 = a0;

    int r = s;
    for (; r + 3 < e; r += 4) {
        float4 v0 = __ldcs(&x[(size_t)(r    ) * 32 + lane]);
        float4 v1 = __ldcs(&x[(size_t)(r + 1) * 32 + lane]);
        float4 v2 = __ldcs(&x[(size_t)(r + 2) * 32 + lane]);
        float4 v3 = __ldcs(&x[(size_t)(r + 3) * 32 + lane]);
        a0 = f4add(a0, v0);
        a1 = f4add(a1, v1);
        a2 = f4add(a2, v2);
        a3 = f4add(a3, v3);
    }
    if (r + 1 < e) {
        float4 v0 = __ldcs(&x[(size_t)(r    ) * 32 + lane]);
        float4 v1 = __ldcs(&x[(size_t)(r + 1) * 32 + lane]);
        a0 = f4add(a0, v0);
        a1 = f4add(a1, v1);
        r += 2;
    }
    if (r < e) {
        a2 = f4add(a2, __ldcs(&x[(size_t)r * 32 + lane]));
    }
    float4 t = f4add(f4add(a0, a1), f4add(a2, a3));

    size_t off = (size_t)gi * 256 + (frag ? 128 : 0) + (size_t)lane * 4;
    *(float4*)(out + off) = t;
}

// ---------------------------------------------------------------------------
extern "C" void kernel_launch(void* const* d_in, const int* in_sizes, int n_in,
                              void* d_out, int out_size)
{
    const float4* xa  = (const float4*)d_in[0];
    const float4* xf  = (const float4*)d_in[1];
    const void*   ba  = d_in[2];
    const void*   bf  = d_in[3];
    float*        out = (float*)d_out;

    int n_atoms = in_sizes[2];
    int n_frags = in_sizes[3];

    const int tpb = 256;
    const int elems_per_blk = tpb * 16;
    int nblk_a = (n_atoms + elems_per_blk - 1) / elems_per_blk;
    int nblk_f = (n_frags + elems_per_blk - 1) / elems_per_blk;
    fill_starts_fused_kernel<<<nblk_a + nblk_f, tpb>>>(ba, n_atoms, bf, n_frags, nblk_a);

    segsum_warp_kernel<<<(2 * NUM_GRAPHS) / 4, 128>>>(xa, xf, out);
    (void)n_in; (void)out_size;
}

// round 11
// speedup vs baseline: 1.0464x; 1.0464x over previous
#include <cuda_runtime.h>

#define NUM_GRAPHS 16384
#define EMB_DIM    128

// Scratch: per-graph start offsets (device globals — no allocation allowed).
__device__ int g_starts_atoms[NUM_GRAPHS + 1];
__device__ int g_starts_frags[NUM_GRAPHS + 1];

// ---------------------------------------------------------------------------
// Fused boundary detection for BOTH index arrays, vectorized: each thread
// owns 8 consecutive elements loaded with two 32B/16B vector loads (+ one
// scalar predecessor load). Already at its 24 MB byte floor (~3 us).
// ---------------------------------------------------------------------------
__global__ void fill_starts_fused_kernel(const void* idx_a, int n_a,
                                         const void* idx_f, int n_f,
                                         int nblk_a)
{
    bool frag = (int)blockIdx.x >= nblk_a;
    const void* idxp = frag ? idx_f : idx_a;
    int         n    = frag ? n_f   : n_a;
    int*        starts = frag ? g_starts_frags : g_starts_atoms;
    int blk = frag ? (blockIdx.x - nblk_a) : blockIdx.x;

    int base = (blk * blockDim.x + threadIdx.x) * 8;
    if (base >= n) return;
    int cnt = n - base; if (cnt > 8) cnt = 8;

    const long long* p64 = (const long long*)idxp;
    const int*       p32 = (const int*)idxp;
    long long probe = p64[n / 4];
    bool is64 = (probe >= 0 && probe < NUM_GRAPHS);

    int v[8];
    if (is64) {
        if (cnt == 8) {
            longlong4 q0 = ((const longlong4*)(p64 + base))[0];
            longlong4 q1 = ((const longlong4*)(p64 + base))[1];
            v[0]=(int)q0.x; v[1]=(int)q0.y; v[2]=(int)q0.z; v[3]=(int)q0.w;
            v[4]=(int)q1.x; v[5]=(int)q1.y; v[6]=(int)q1.z; v[7]=(int)q1.w;
        } else {
            for (int j = 0; j < cnt; ++j) v[j] = (int)p64[base + j];
        }
    } else {
        if (cnt == 8) {
            int4 q0 = ((const int4*)(p32 + base))[0];
            int4 q1 = ((const int4*)(p32 + base))[1];
            v[0]=q0.x; v[1]=q0.y; v[2]=q0.z; v[3]=q0.w;
            v[4]=q1.x; v[5]=q1.y; v[6]=q1.z; v[7]=q1.w;
        } else {
            for (int j = 0; j < cnt; ++j) v[j] = p32[base + j];
        }
    }

    int prev = (base == 0) ? -1 : (is64 ? (int)p64[base - 1] : p32[base - 1]);

    #pragma unroll
    for (int j = 0; j < 8; ++j) {
        if (j >= cnt) break;
        int b = v[j];
        for (int g = prev + 1; g <= b; ++g) starts[g] = base + j;
        prev = b;
    }
    if (base + cnt == n) {
        for (int g = prev + 1; g <= NUM_GRAPHS; ++g) starts[g] = n;
    }
}

// ---------------------------------------------------------------------------
// Segment sum: one CTA per (graph, half), 128 threads = 4 warps. Lane l owns
// float4 columns [4l,4l+4); a warp's LDG.128s cover a full 512B row. Warps
// stride rows by 4 with a 6-deep unroll -> 24 in-flight 128b loads per CTA.
// 4-deep + scalar remainder for tails. (Best measured total: 223.74 us.)
// ---------------------------------------------------------------------------
__device__ __forceinline__ float4 f4add(float4 a, float4 b) {
    a.x += b.x; a.y += b.y; a.z += b.z; a.w += b.w; return a;
}

__global__ __launch_bounds__(128) void segsum_kernel(
    const float4* __restrict__ xa,
    const float4* __restrict__ xf,
    float* __restrict__ out)
{
    int bid   = blockIdx.x;
    bool frag = bid >= NUM_GRAPHS;
    int gi    = frag ? bid - NUM_GRAPHS : bid;

    const int* starts = frag ? g_starts_frags : g_starts_atoms;
    const float4* x   = frag ? xf : xa;

    int s = starts[gi];
    int e = starts[gi + 1];

    int w    = threadIdx.x >> 5;
    int lane = threadIdx.x & 31;

    float4 a0 = make_float4(0.f, 0.f, 0.f, 0.f);
    float4 a1 = a0, a2 = a0, a3 = a0, a4 = a0, a5 = a0;

    int r = s + w;
    // Main loop: 6 independent LDG.128 per thread per iteration.
    for (; r + 20 < e; r += 24) {
        float4 v0 = __ldcs(&x[(size_t)(r     ) * 32 + lane]);
        float4 v1 = __ldcs(&x[(size_t)(r +  4) * 32 + lane]);
        float4 v2 = __ldcs(&x[(size_t)(r +  8) * 32 + lane]);
        float4 v3 = __ldcs(&x[(size_t)(r + 12) * 32 + lane]);
        float4 v4 = __ldcs(&x[(size_t)(r + 16) * 32 + lane]);
        float4 v5 = __ldcs(&x[(size_t)(r + 20) * 32 + lane]);
        a0 = f4add(a0, v0);
        a1 = f4add(a1, v1);
        a2 = f4add(a2, v2);
        a3 = f4add(a3, v3);
        a4 = f4add(a4, v4);
        a5 = f4add(a5, v5);
    }
    // 4-deep remainder (runs at most once).
    if (r + 12 < e) {
        float4 v0 = __ldcs(&x[(size_t)(r     ) * 32 + lane]);
        float4 v1 = __ldcs(&x[(size_t)(r +  4) * 32 + lane]);
        float4 v2 = __ldcs(&x[(size_t)(r +  8) * 32 + lane]);
        float4 v3 = __ldcs(&x[(size_t)(r + 12) * 32 + lane]);
        a0 = f4add(a0, v0);
        a1 = f4add(a1, v1);
        a2 = f4add(a2, v2);
        a3 = f4add(a3, v3);
        r += 16;
    }
    for (; r < e; r += 4) {
        a0 = f4add(a0, __ldcs(&x[(size_t)r * 32 + lane]));
    }
    a0 = f4add(f4add(f4add(a0, a1), f4add(a2, a3)), f4add(a4, a5));

    __shared__ float4 sred[4][32];
    sred[w][lane] = a0;
    __syncthreads();

    if (w == 0) {
        float4 t = f4add(f4add(sred[0][lane], sred[1][lane]),
                         f4add(sred[2][lane], sred[3][lane]));
        size_t off = (size_t)gi * 256 + (frag ? 128 : 0) + (size_t)lane * 4;
        *(float4*)(out + off) = t;
    }
}

// ---------------------------------------------------------------------------
extern "C" void kernel_launch(void* const* d_in, const int* in_sizes, int n_in,
                              void* d_out, int out_size)
{
    const float4* xa  = (const float4*)d_in[0];
    const float4* xf  = (const float4*)d_in[1];
    const void*   ba  = d_in[2];
    const void*   bf  = d_in[3];
    float*        out = (float*)d_out;

    int n_atoms = in_sizes[2];
    int n_frags = in_sizes[3];

    const int tpb = 256;
    const int elems_per_blk = tpb * 8;
    int nblk_a = (n_atoms + elems_per_blk - 1) / elems_per_blk;
    int nblk_f = (n_frags + elems_per_blk - 1) / elems_per_blk;
    fill_starts_fused_kernel<<<nblk_a + nblk_f, tpb>>>(ba, n_atoms, bf, n_frags, nblk_a);

    segsum_kernel<<<2 * NUM_GRAPHS, 128>>>(xa, xf, out);
    (void)n_in; (void)out_size;
}